// round 3
// baseline (speedup 1.0000x reference)
#include <cuda_runtime.h>
#include <stdint.h>

#define N_NODES   10000
#define ROW_WORDS 320      // padded row stride in 32-bit words
#define USED_WORDS 313     // ceil(10000/32)
#define D         256
#define E_EDGES   320000

// ---- scratch (no allocations allowed; __device__ globals) ----
__device__ unsigned int g_bits[N_NODES * ROW_WORDS];   // 12.8 MB bitmask adjacency
__device__ float        g_dinv[N_NODES];               // 40 KB
__device__ float        g_z[N_NODES * D];              // 10.24 MB  z = dinv * x
__device__ float        g_h[N_NODES * D];              // 10.24 MB  aggregated

// ---------------------------------------------------------------------------
__global__ void zero_bits_kernel() {
    int idx    = blockIdx.x * blockDim.x + threadIdx.x;
    int stride = gridDim.x * blockDim.x;
    for (int i = idx; i < N_NODES * ROW_WORDS; i += stride) g_bits[i] = 0u;
}

// Dedup via bitmask: set semantics of the reference (at[...].max) for free.
// Edges read as int32 (harness converts integer inputs to int32 per stub docs).
// Bounds guard: if the dtype assumption is ever wrong we produce a finite
// wrong answer (diagnosable via rel_err) instead of a device fault.
__global__ void edge_kernel(const int* __restrict__ ei) {
    int e = blockIdx.x * blockDim.x + threadIdx.x;
    if (e >= E_EDGES) return;
    int s = ei[e];
    int d = ei[E_EDGES + e];
    if ((unsigned)s >= N_NODES || (unsigned)d >= N_NODES) return;
    atomicOr(&g_bits[s * ROW_WORDS + (d >> 5)], 1u << (d & 31));
    atomicOr(&g_bits[d * ROW_WORDS + (s >> 5)], 1u << (s & 31));
}

// deg[i] = popcount(row i) + 1   (identity adds 1; self-edge bit already counted)
__global__ void degree_kernel() {
    int warp = (blockIdx.x * blockDim.x + threadIdx.x) >> 5;
    int lane = threadIdx.x & 31;
    if (warp >= N_NODES) return;
    const unsigned int* row = &g_bits[warp * ROW_WORDS];
    int cnt = 0;
    for (int w = lane; w < USED_WORDS; w += 32) cnt += __popc(row[w]);
    #pragma unroll
    for (int off = 16; off; off >>= 1) cnt += __shfl_down_sync(0xffffffffu, cnt, off);
    if (lane == 0) g_dinv[warp] = rsqrtf((float)(cnt + 1));
}

__global__ void scale_kernel(const float* __restrict__ x) {
    int i = blockIdx.x;
    int t = threadIdx.x;
    g_z[i * D + t] = g_dinv[i] * x[i * D + t];
}

// One block per node. Thread t owns output column t.
// h[i] = dinv[i] * ( sum_{bit j set} z[j] + z[i] )
// The extra z[i] is the identity (self-loop) term; a set self-bit correctly
// yields total diagonal coefficient 2*dinv[i]^2, matching adj[i,i]=2.
__global__ void agg_kernel() {
    __shared__ unsigned int words[USED_WORDS];
    int i = blockIdx.x;
    int t = threadIdx.x;
    const unsigned int* row = &g_bits[i * ROW_WORDS];
    for (int w = t; w < USED_WORDS; w += blockDim.x) words[w] = row[w];
    __syncthreads();

    float acc = g_z[i * D + t];   // identity term
    #pragma unroll 1
    for (int wi = 0; wi < USED_WORDS; wi++) {
        unsigned int w = words[wi];   // uniform across block -> no divergence
        while (w) {
            int b = __ffs(w) - 1;
            w &= w - 1;
            int j = (wi << 5) + b;
            acc += g_z[j * D + t];    // coalesced 128B per warp, L2-resident
        }
    }
    g_h[i * D + t] = acc * g_dinv[i];
}

// ---------------------------------------------------------------------------
// out[10000,256] = h[10000,256] @ W[256,256], fp32 tiled SGEMM
#define BM 64
#define BN 64
#define BK 16
__global__ void gemm_kernel(const float* __restrict__ Wt, float* __restrict__ out) {
    __shared__ __align__(16) float As[BK][BM];
    __shared__ __align__(16) float Bs[BK][BN];

    int bm  = blockIdx.y * BM;
    int bn  = blockIdx.x * BN;
    int tid = threadIdx.x;            // 256 threads
    int tx  = tid & 15;               // n direction (16 x 4)
    int ty  = tid >> 4;               // m direction (16 x 4)

    float acc[4][4] = {};

    for (int k0 = 0; k0 < D; k0 += BK) {
        // A tile 64(m) x 16(k): each thread one float4 along k
        {
            int m  = tid >> 2;            // 0..63
            int kg = (tid & 3) * 4;       // 0,4,8,12
            int gm = bm + m;
            float4 av = make_float4(0.f, 0.f, 0.f, 0.f);
            if (gm < N_NODES)
                av = *reinterpret_cast<const float4*>(&g_h[gm * D + k0 + kg]);
            As[kg + 0][m] = av.x;
            As[kg + 1][m] = av.y;
            As[kg + 2][m] = av.z;
            As[kg + 3][m] = av.w;
        }
        // B tile 16(k) x 64(n): each thread one float4 along n (coalesced)
        {
            int kb = tid >> 4;            // 0..15
            int nb = (tid & 15) * 4;      // 0..60
            float4 bv = *reinterpret_cast<const float4*>(&Wt[(k0 + kb) * D + bn + nb]);
            *reinterpret_cast<float4*>(&Bs[kb][nb]) = bv;
        }
        __syncthreads();

        #pragma unroll
        for (int k = 0; k < BK; k++) {
            float4 a = *reinterpret_cast<const float4*>(&As[k][ty * 4]);
            float4 b = *reinterpret_cast<const float4*>(&Bs[k][tx * 4]);
            float ar[4] = {a.x, a.y, a.z, a.w};
            float br[4] = {b.x, b.y, b.z, b.w};
            #pragma unroll
            for (int r = 0; r < 4; r++)
                #pragma unroll
                for (int c = 0; c < 4; c++)
                    acc[r][c] += ar[r] * br[c];
        }
        __syncthreads();
    }

    #pragma unroll
    for (int r = 0; r < 4; r++) {
        int gm = bm + ty * 4 + r;
        if (gm >= N_NODES) continue;
        float4 v = make_float4(acc[r][0], acc[r][1], acc[r][2], acc[r][3]);
        *reinterpret_cast<float4*>(&out[gm * D + bn + tx * 4]) = v;
    }
}

// ---------------------------------------------------------------------------
extern "C" void kernel_launch(void* const* d_in, const int* in_sizes, int n_in,
                              void* d_out, int out_size) {
    // Dispatch inputs by element count (robust to metadata ordering):
    //   x: 10000*256 = 2,560,000   edge_index: 2*320000 = 640,000   weight: 256*256 = 65,536
    const float* x  = nullptr;
    const int*   ei = nullptr;
    const float* w  = nullptr;
    for (int i = 0; i < n_in; i++) {
        if      (in_sizes[i] == N_NODES * D)   x  = (const float*)d_in[i];
        else if (in_sizes[i] == 2 * E_EDGES)   ei = (const int*)d_in[i];
        else if (in_sizes[i] == D * D)         w  = (const float*)d_in[i];
    }
    float* out = (float*)d_out;
    (void)out_size;

    zero_bits_kernel<<<1024, 256>>>();
    edge_kernel<<<(E_EDGES + 255) / 256, 256>>>(ei);
    degree_kernel<<<(N_NODES * 32 + 255) / 256, 256>>>();
    scale_kernel<<<N_NODES, D>>>(x);
    agg_kernel<<<N_NODES, D>>>();
    dim3 ggrid(D / BN, (N_NODES + BM - 1) / BM);
    gemm_kernel<<<ggrid, 256>>>(w, out);
}

// round 5
// speedup vs baseline: 2.8992x; 2.8992x over previous
#include <cuda_runtime.h>
#include <stdint.h>

#define N_NODES   10000
#define ROW_WORDS 320      // padded row stride in 32-bit words
#define USED_WORDS 313     // ceil(10000/32)
#define D         256
#define E_EDGES   320000
#define CAP       2048     // shared neighbor-list capacity (max real degree ~110)

// ---- scratch (no allocations allowed; __device__ globals) ----
__device__ unsigned int g_bits[N_NODES * ROW_WORDS];   // 12.8 MB bitmask adjacency
__device__ float        g_dinv[N_NODES];               // 40 KB
__device__ float        g_z[N_NODES * D];              // 10.24 MB  z = dinv ⊙ (x @ W)

// ---------------------------------------------------------------------------
__global__ void zero_bits_kernel() {
    int idx    = blockIdx.x * blockDim.x + threadIdx.x;
    int stride = gridDim.x * blockDim.x;
    uint4 zz = make_uint4(0u, 0u, 0u, 0u);
    uint4* p = reinterpret_cast<uint4*>(g_bits);
    for (int i = idx; i < N_NODES * ROW_WORDS / 4; i += stride) p[i] = zz;
}

// Dedup via bitmask: set semantics of the reference (at[...].max) for free.
__global__ void edge_kernel(const int* __restrict__ ei) {
    int e = blockIdx.x * blockDim.x + threadIdx.x;
    if (e >= E_EDGES) return;
    int s = ei[e];
    int d = ei[E_EDGES + e];
    if ((unsigned)s >= N_NODES || (unsigned)d >= N_NODES) return;
    atomicOr(&g_bits[s * ROW_WORDS + (d >> 5)], 1u << (d & 31));
    atomicOr(&g_bits[d * ROW_WORDS + (s >> 5)], 1u << (s & 31));
}

// deg[i] = popcount(row i) + 1 (identity); dinv = rsqrt(deg)
__global__ void degree_kernel() {
    int warp = (blockIdx.x * blockDim.x + threadIdx.x) >> 5;
    int lane = threadIdx.x & 31;
    if (warp >= N_NODES) return;
    const unsigned int* row = &g_bits[warp * ROW_WORDS];
    int cnt = 0;
    for (int w = lane; w < USED_WORDS; w += 32) cnt += __popc(row[w]);
    #pragma unroll
    for (int off = 16; off; off >>= 1) cnt += __shfl_down_sync(0xffffffffu, cnt, off);
    if (lane == 0) g_dinv[warp] = rsqrtf((float)(cnt + 1));
}

// ---------------------------------------------------------------------------
// g_z[10000,256] = dinv[:,None] * (x[10000,256] @ W[256,256])
// BM=128, BN=64, BK=16, 256 threads, 8x4 microtile (compute-bound config).
#define BM 128
#define BN 64
#define BK 16
__global__ void gemm_scale_kernel(const float* __restrict__ X,
                                  const float* __restrict__ W) {
    __shared__ __align__(16) float As[BK][BM];
    __shared__ __align__(16) float Bs[BK][BN];

    int bm  = blockIdx.y * BM;
    int bn  = blockIdx.x * BN;
    int tid = threadIdx.x;            // 256 threads
    int tx  = tid & 15;               // n dir: 16 x 4 = 64
    int ty  = tid >> 4;               // m dir: 16 x 8 = 128

    float acc[8][4] = {};

    for (int k0 = 0; k0 < D; k0 += BK) {
        // A tile 128(m) x 16(k): each thread two float4 along k
        {
            int m  = tid >> 1;            // 0..127
            int kg = (tid & 1) * 8;       // 0 or 8
            int gm = bm + m;
            float4 a0 = make_float4(0.f, 0.f, 0.f, 0.f);
            float4 a1 = make_float4(0.f, 0.f, 0.f, 0.f);
            if (gm < N_NODES) {
                a0 = *reinterpret_cast<const float4*>(&X[gm * D + k0 + kg]);
                a1 = *reinterpret_cast<const float4*>(&X[gm * D + k0 + kg + 4]);
            }
            As[kg + 0][m] = a0.x; As[kg + 1][m] = a0.y;
            As[kg + 2][m] = a0.z; As[kg + 3][m] = a0.w;
            As[kg + 4][m] = a1.x; As[kg + 5][m] = a1.y;
            As[kg + 6][m] = a1.z; As[kg + 7][m] = a1.w;
        }
        // B tile 16(k) x 64(n): each thread one float4 along n (coalesced)
        {
            int kb = tid >> 4;            // 0..15
            int nb = (tid & 15) * 4;      // 0..60
            float4 bv = *reinterpret_cast<const float4*>(&W[(k0 + kb) * D + bn + nb]);
            *reinterpret_cast<float4*>(&Bs[kb][nb]) = bv;
        }
        __syncthreads();

        #pragma unroll
        for (int k = 0; k < BK; k++) {
            float4 alo = *reinterpret_cast<const float4*>(&As[k][ty * 8]);
            float4 ahi = *reinterpret_cast<const float4*>(&As[k][ty * 8 + 4]);
            float4 b   = *reinterpret_cast<const float4*>(&Bs[k][tx * 4]);
            float ar[8] = {alo.x, alo.y, alo.z, alo.w, ahi.x, ahi.y, ahi.z, ahi.w};
            float br[4] = {b.x, b.y, b.z, b.w};
            #pragma unroll
            for (int r = 0; r < 8; r++)
                #pragma unroll
                for (int c = 0; c < 4; c++)
                    acc[r][c] += ar[r] * br[c];
        }
        __syncthreads();
    }

    #pragma unroll
    for (int r = 0; r < 8; r++) {
        int gm = bm + ty * 8 + r;
        if (gm >= N_NODES) continue;
        float dv = g_dinv[gm];
        float4 v = make_float4(acc[r][0] * dv, acc[r][1] * dv,
                               acc[r][2] * dv, acc[r][3] * dv);
        *reinterpret_cast<float4*>(&g_z[gm * D + bn + tx * 4]) = v;
    }
}

// ---------------------------------------------------------------------------
// One block per node i, thread t owns column t.
// out[i] = dinv[i] * ( sum_{bit j set} z[j] + z[i] )
// Phase 1: expand bitmask row into shared index list (dedup already in bits).
// Phase 2: unroll-8 gather -> 8 outstanding L2 loads (latency hiding).
__global__ void agg_kernel(float* __restrict__ out) {
    __shared__ unsigned int words[USED_WORDS];
    __shared__ int list[CAP];
    __shared__ int s_count;
    int i = blockIdx.x;
    int t = threadIdx.x;
    if (t == 0) s_count = 0;
    const unsigned int* row = &g_bits[i * ROW_WORDS];
    for (int w = t; w < USED_WORDS; w += 256) words[w] = row[w];
    __syncthreads();

    // extract set-bit indices into list
    for (int w = t; w < USED_WORDS; w += 256) {
        unsigned int m = words[w];
        int n = __popc(m);
        if (n) {
            int base = atomicAdd(&s_count, n);
            while (m) {
                int b = __ffs(m) - 1;
                m &= m - 1;
                if (base < CAP) list[base] = (w << 5) + b;
                base++;
            }
        }
    }
    __syncthreads();

    float acc = g_z[i * D + t];   // identity (self-loop) term
    int c = s_count;

    if (c <= CAP) {
        int k = 0;
        for (; k + 8 <= c; k += 8) {
            int j0 = list[k+0], j1 = list[k+1], j2 = list[k+2], j3 = list[k+3];
            int j4 = list[k+4], j5 = list[k+5], j6 = list[k+6], j7 = list[k+7];
            float a0 = g_z[j0 * D + t], a1 = g_z[j1 * D + t];
            float a2 = g_z[j2 * D + t], a3 = g_z[j3 * D + t];
            float a4 = g_z[j4 * D + t], a5 = g_z[j5 * D + t];
            float a6 = g_z[j6 * D + t], a7 = g_z[j7 * D + t];
            acc += ((a0 + a1) + (a2 + a3)) + ((a4 + a5) + (a6 + a7));
        }
        for (; k + 4 <= c; k += 4) {
            int j0 = list[k+0], j1 = list[k+1], j2 = list[k+2], j3 = list[k+3];
            float a0 = g_z[j0 * D + t], a1 = g_z[j1 * D + t];
            float a2 = g_z[j2 * D + t], a3 = g_z[j3 * D + t];
            acc += (a0 + a1) + (a2 + a3);
        }
        for (; k < c; k++) acc += g_z[list[k] * D + t];
    } else {
        // overflow fallback (never triggers for this dataset; correctness net)
        #pragma unroll 1
        for (int wi = 0; wi < USED_WORDS; wi++) {
            unsigned int w = words[wi];
            while (w) {
                int b = __ffs(w) - 1;
                w &= w - 1;
                acc += g_z[((wi << 5) + b) * D + t];
            }
        }
    }
    out[i * D + t] = acc * g_dinv[i];
}

// ---------------------------------------------------------------------------
extern "C" void kernel_launch(void* const* d_in, const int* in_sizes, int n_in,
                              void* d_out, int out_size) {
    // Dispatch inputs by element count (robust to metadata ordering)
    const float* x  = nullptr;
    const int*   ei = nullptr;
    const float* w  = nullptr;
    for (int i = 0; i < n_in; i++) {
        if      (in_sizes[i] == N_NODES * D)   x  = (const float*)d_in[i];
        else if (in_sizes[i] == 2 * E_EDGES)   ei = (const int*)d_in[i];
        else if (in_sizes[i] == D * D)         w  = (const float*)d_in[i];
    }
    float* out = (float*)d_out;
    (void)out_size;

    zero_bits_kernel<<<1024, 256>>>();
    edge_kernel<<<(E_EDGES + 255) / 256, 256>>>(ei);
    degree_kernel<<<(N_NODES * 32 + 255) / 256, 256>>>();
    dim3 ggrid(D / BN, (N_NODES + BM - 1) / BM);
    gemm_scale_kernel<<<ggrid, 256>>>(x, w);
    agg_kernel<<<N_NODES, 256>>>(out);
}

// round 8
// speedup vs baseline: 3.3229x; 1.1462x over previous
#include <cuda_runtime.h>
#include <cuda_fp16.h>
#include <stdint.h>

#define N_NODES   10000
#define ROW_WORDS 320      // padded row stride in 32-bit words
#define USED_WORDS 313     // ceil(10000/32)
#define D         256
#define E_EDGES   320000
#define CAP       2048     // shared neighbor-list capacity (max real degree ~110)

// ---- scratch (no allocations allowed; __device__ globals) ----
__device__ unsigned int g_bits[N_NODES * ROW_WORDS];   // 12.8 MB bitmask adjacency
__device__ float        g_dinv[N_NODES];               // 40 KB
__device__ __half       g_zh[N_NODES * D];             // 5.12 MB  z = dinv ⊙ (x @ W), fp16

// ---------------------------------------------------------------------------
__global__ void zero_bits_kernel() {
    int idx    = blockIdx.x * blockDim.x + threadIdx.x;
    int stride = gridDim.x * blockDim.x;
    uint4 zz = make_uint4(0u, 0u, 0u, 0u);
    uint4* p = reinterpret_cast<uint4*>(g_bits);
    for (int i = idx; i < N_NODES * ROW_WORDS / 4; i += stride) p[i] = zz;
}

// Dedup via bitmask: set semantics of the reference (at[...].max) for free.
__global__ void edge_kernel(const int* __restrict__ ei) {
    int e = blockIdx.x * blockDim.x + threadIdx.x;
    if (e >= E_EDGES) return;
    int s = ei[e];
    int d = ei[E_EDGES + e];
    if ((unsigned)s >= N_NODES || (unsigned)d >= N_NODES) return;
    atomicOr(&g_bits[s * ROW_WORDS + (d >> 5)], 1u << (d & 31));
    atomicOr(&g_bits[d * ROW_WORDS + (s >> 5)], 1u << (s & 31));
}

// deg[i] = popcount(row i) + 1 (identity); dinv = rsqrt(deg)
__global__ void degree_kernel() {
    int warp = (blockIdx.x * blockDim.x + threadIdx.x) >> 5;
    int lane = threadIdx.x & 31;
    if (warp >= N_NODES) return;
    const unsigned int* row = &g_bits[warp * ROW_WORDS];
    int cnt = 0;
    for (int w = lane; w < USED_WORDS; w += 32) cnt += __popc(row[w]);
    #pragma unroll
    for (int off = 16; off; off >>= 1) cnt += __shfl_down_sync(0xffffffffu, cnt, off);
    if (lane == 0) g_dinv[warp] = rsqrtf((float)(cnt + 1));
}

// ---------------------------------------------------------------------------
// g_zh[10000,256] = fp16( dinv[:,None] * (x @ W) )
// BM=64, BN=128, BK=16, 128 threads, 8x8 microtile: 64 FFMA per 4 LDS.128.
#define BM 64
#define BN 128
#define BK 16
__global__ __launch_bounds__(128) void gemm_scale_kernel(const float* __restrict__ X,
                                                         const float* __restrict__ W) {
    __shared__ __align__(16) float As[BK][BM];
    __shared__ __align__(16) float Bs[BK][BN];

    int bm  = blockIdx.y * BM;
    int bn  = blockIdx.x * BN;
    int tid = threadIdx.x;            // 128 threads
    int tx  = tid & 15;               // n dir: 16 x 8 = 128
    int ty  = tid >> 4;               // m dir:  8 x 8 = 64

    float acc[8][8] = {};

    for (int k0 = 0; k0 < D; k0 += BK) {
        // A tile 64(m) x 16(k): each thread 8 floats (2 float4) along k
        {
            int m  = tid >> 1;            // 0..63
            int kg = (tid & 1) * 8;       // 0 or 8
            int gm = bm + m;
            float4 a0 = make_float4(0.f, 0.f, 0.f, 0.f);
            float4 a1 = make_float4(0.f, 0.f, 0.f, 0.f);
            if (gm < N_NODES) {
                a0 = *reinterpret_cast<const float4*>(&X[gm * D + k0 + kg]);
                a1 = *reinterpret_cast<const float4*>(&X[gm * D + k0 + kg + 4]);
            }
            As[kg + 0][m] = a0.x; As[kg + 1][m] = a0.y;
            As[kg + 2][m] = a0.z; As[kg + 3][m] = a0.w;
            As[kg + 4][m] = a1.x; As[kg + 5][m] = a1.y;
            As[kg + 6][m] = a1.z; As[kg + 7][m] = a1.w;
        }
        // B tile 16(k) x 128(n): 4 float4 per thread, lanes contiguous per load
        {
            int kb = tid >> 3;            // 0..15
            int n0 = (tid & 7) * 4;       // 0..28
            #pragma unroll
            for (int l = 0; l < 4; l++) {
                int n = n0 + l * 32;
                float4 bv = *reinterpret_cast<const float4*>(&W[(k0 + kb) * D + bn + n]);
                *reinterpret_cast<float4*>(&Bs[kb][n]) = bv;
            }
        }
        __syncthreads();

        #pragma unroll
        for (int k = 0; k < BK; k++) {
            float4 alo = *reinterpret_cast<const float4*>(&As[k][ty * 8]);
            float4 ahi = *reinterpret_cast<const float4*>(&As[k][ty * 8 + 4]);
            float4 blo = *reinterpret_cast<const float4*>(&Bs[k][tx * 8]);
            float4 bhi = *reinterpret_cast<const float4*>(&Bs[k][tx * 8 + 4]);
            float ar[8] = {alo.x, alo.y, alo.z, alo.w, ahi.x, ahi.y, ahi.z, ahi.w};
            float br[8] = {blo.x, blo.y, blo.z, blo.w, bhi.x, bhi.y, bhi.z, bhi.w};
            #pragma unroll
            for (int r = 0; r < 8; r++)
                #pragma unroll
                for (int c = 0; c < 8; c++)
                    acc[r][c] += ar[r] * br[c];
        }
        __syncthreads();
    }

    #pragma unroll
    for (int r = 0; r < 8; r++) {
        int gm = bm + ty * 8 + r;
        if (gm >= N_NODES) continue;
        float dv = g_dinv[gm];
        __half2 h[4];
        #pragma unroll
        for (int c = 0; c < 4; c++)
            h[c] = __floats2half2_rn(acc[r][2*c] * dv, acc[r][2*c+1] * dv);
        *reinterpret_cast<uint4*>(&g_zh[gm * D + bn + tx * 8]) =
            *reinterpret_cast<uint4*>(h);
    }
}

// ---------------------------------------------------------------------------
// One block (128 threads) per node i; thread t owns columns 2t, 2t+1 (half2).
// out[i] = dinv[i] * ( sum_{bit j set} z[j] + z[i] )   (fp32 accumulate)
__global__ __launch_bounds__(128) void agg_kernel(float* __restrict__ out) {
    __shared__ unsigned int words[USED_WORDS];
    __shared__ int list[CAP];
    __shared__ int s_count;
    int i = blockIdx.x;
    int t = threadIdx.x;
    if (t == 0) s_count = 0;
    const unsigned int* row = &g_bits[i * ROW_WORDS];
    for (int w = t; w < USED_WORDS; w += 128) words[w] = row[w];
    __syncthreads();

    // extract set-bit indices into list (dedup already encoded in bits)
    for (int w = t; w < USED_WORDS; w += 128) {
        unsigned int m = words[w];
        int n = __popc(m);
        if (n) {
            int base = atomicAdd(&s_count, n);
            while (m) {
                int b = __ffs(m) - 1;
                m &= m - 1;
                if (base < CAP) list[base] = (w << 5) + b;
                base++;
            }
        }
    }
    __syncthreads();

    const __half2* Z = reinterpret_cast<const __half2*>(g_zh);  // [node][128]
    float2 self = __half22float2(Z[i * (D / 2) + t]);
    float accx = self.x, accy = self.y;   // identity (self-loop) term
    int c = s_count;

    if (c <= CAP) {
        int k = 0;
        for (; k + 8 <= c; k += 8) {
            float2 a0 = __half22float2(Z[list[k+0] * (D/2) + t]);
            float2 a1 = __half22float2(Z[list[k+1] * (D/2) + t]);
            float2 a2 = __half22float2(Z[list[k+2] * (D/2) + t]);
            float2 a3 = __half22float2(Z[list[k+3] * (D/2) + t]);
            float2 a4 = __half22float2(Z[list[k+4] * (D/2) + t]);
            float2 a5 = __half22float2(Z[list[k+5] * (D/2) + t]);
            float2 a6 = __half22float2(Z[list[k+6] * (D/2) + t]);
            float2 a7 = __half22float2(Z[list[k+7] * (D/2) + t]);
            accx += ((a0.x + a1.x) + (a2.x + a3.x)) + ((a4.x + a5.x) + (a6.x + a7.x));
            accy += ((a0.y + a1.y) + (a2.y + a3.y)) + ((a4.y + a5.y) + (a6.y + a7.y));
        }
        for (; k < c; k++) {
            float2 a = __half22float2(Z[list[k] * (D/2) + t]);
            accx += a.x; accy += a.y;
        }
    } else {
        // overflow fallback (never triggers for this dataset; correctness net)
        #pragma unroll 1
        for (int wi = 0; wi < USED_WORDS; wi++) {
            unsigned int w = words[wi];
            while (w) {
                int b = __ffs(w) - 1;
                w &= w - 1;
                float2 a = __half22float2(Z[((wi << 5) + b) * (D/2) + t]);
                accx += a.x; accy += a.y;
            }
        }
    }
    float dv = g_dinv[i];
    float2 o = make_float2(accx * dv, accy * dv);
    *reinterpret_cast<float2*>(&out[i * D + 2 * t]) = o;
}

// ---------------------------------------------------------------------------
extern "C" void kernel_launch(void* const* d_in, const int* in_sizes, int n_in,
                              void* d_out, int out_size) {
    // Dispatch inputs by element count (robust to metadata ordering)
    const float* x  = nullptr;
    const int*   ei = nullptr;
    const float* w  = nullptr;
    for (int i = 0; i < n_in; i++) {
        if      (in_sizes[i] == N_NODES * D)   x  = (const float*)d_in[i];
        else if (in_sizes[i] == 2 * E_EDGES)   ei = (const int*)d_in[i];
        else if (in_sizes[i] == D * D)         w  = (const float*)d_in[i];
    }
    float* out = (float*)d_out;
    (void)out_size;

    zero_bits_kernel<<<1024, 256>>>();
    edge_kernel<<<(E_EDGES + 255) / 256, 256>>>(ei);
    degree_kernel<<<(N_NODES * 32 + 255) / 256, 256>>>();
    dim3 ggrid(D / BN, (N_NODES + BM - 1) / BM);
    gemm_scale_kernel<<<ggrid, 128>>>(x, w);
    agg_kernel<<<N_NODES, 128>>>(out);
}

// round 10
// speedup vs baseline: 3.3756x; 1.0159x over previous
#include <cuda_runtime.h>
#include <cuda_fp16.h>
#include <cuda_bf16.h>
#include <stdint.h>

#define N_NODES   10000
#define ROW_WORDS 320      // padded row stride in 32-bit words
#define USED_WORDS 313     // ceil(10000/32)
#define D         256
#define DW        128      // D in b32 words (2 bf16 each)
#define E_EDGES   320000
#define CAP       2048

// ---- scratch (__device__ globals; no allocations allowed) ----
__device__ unsigned g_bits[N_NODES * ROW_WORDS];   // 12.8 MB bitmask adjacency
__device__ float    g_dinv[N_NODES];
__device__ __half   g_zh[N_NODES * D];             // z = dinv ⊙ (x @ W), fp16
__device__ unsigned g_xh[N_NODES * DW];            // x hi split, packed bf16x2
__device__ unsigned g_xl[N_NODES * DW];            // x lo split
__device__ unsigned g_wth[D * DW];                 // W^T hi split [n][k], packed
__device__ unsigned g_wtl[D * DW];                 // W^T lo split

// ---------------------------------------------------------------------------
__global__ void zero_bits_kernel() {
    int idx    = blockIdx.x * blockDim.x + threadIdx.x;
    int stride = gridDim.x * blockDim.x;
    uint4 zz = make_uint4(0u, 0u, 0u, 0u);
    uint4* p = reinterpret_cast<uint4*>(g_bits);
    for (int i = idx; i < N_NODES * ROW_WORDS / 4; i += stride) p[i] = zz;
}

__global__ void edge_kernel(const int* __restrict__ ei) {
    int e = blockIdx.x * blockDim.x + threadIdx.x;
    if (e >= E_EDGES) return;
    int s = ei[e];
    int d = ei[E_EDGES + e];
    if ((unsigned)s >= N_NODES || (unsigned)d >= N_NODES) return;
    atomicOr(&g_bits[s * ROW_WORDS + (d >> 5)], 1u << (d & 31));
    atomicOr(&g_bits[d * ROW_WORDS + (s >> 5)], 1u << (s & 31));
}

__global__ void degree_kernel() {
    int warp = (blockIdx.x * blockDim.x + threadIdx.x) >> 5;
    int lane = threadIdx.x & 31;
    if (warp >= N_NODES) return;
    const unsigned* row = &g_bits[warp * ROW_WORDS];
    int cnt = 0;
    for (int w = lane; w < USED_WORDS; w += 32) cnt += __popc(row[w]);
    #pragma unroll
    for (int off = 16; off; off >>= 1) cnt += __shfl_down_sync(0xffffffffu, cnt, off);
    if (lane == 0) g_dinv[warp] = rsqrtf((float)(cnt + 1));
}

// ---------------------------------------------------------------------------
// Split fp32 -> bf16 hi + bf16 lo (packed 2 per word; low 16 bits = even col).
__device__ __forceinline__ unsigned pack_bf16(float a, float b) {
    __nv_bfloat16 ba = __float2bfloat16(a);
    __nv_bfloat16 bb = __float2bfloat16(b);
    return (unsigned)__bfloat16_as_ushort(ba) |
           ((unsigned)__bfloat16_as_ushort(bb) << 16);
}

__global__ void split_x_kernel(const float* __restrict__ X) {
    int idx = blockIdx.x * blockDim.x + threadIdx.x;   // over N_NODES*DW
    if (idx >= N_NODES * DW) return;
    int m = idx >> 7, w = idx & 127;
    float v0 = X[m * D + 2 * w], v1 = X[m * D + 2 * w + 1];
    float h0 = __bfloat162float(__float2bfloat16(v0));
    float h1 = __bfloat162float(__float2bfloat16(v1));
    g_xh[idx] = pack_bf16(v0, v1);
    g_xl[idx] = pack_bf16(v0 - h0, v1 - h1);
}

// W is [k][n] row-major; write W^T hi/lo as [n][k] packed words.
__global__ void split_w_kernel(const float* __restrict__ W) {
    int idx = blockIdx.x * blockDim.x + threadIdx.x;   // over D*DW
    if (idx >= D * DW) return;
    int n = idx >> 7, w = idx & 127;
    float v0 = W[(2 * w) * D + n], v1 = W[(2 * w + 1) * D + n];
    float h0 = __bfloat162float(__float2bfloat16(v0));
    float h1 = __bfloat162float(__float2bfloat16(v1));
    g_wth[idx] = pack_bf16(v0, v1);
    g_wtl[idx] = pack_bf16(v0 - h0, v1 - h1);
}

// ---------------------------------------------------------------------------
// Tensor-core GEMM: g_zh = fp16( dinv ⊙ (x @ W) )
// Block: 256 thr (8 warps), tile 128(M) x 64(N). Warp w owns rows [16w,16w+16).
// mma.sync.m16n8k16 bf16, fp32 acc; 3-mma split per fragment pair.
// W^T tile staged in smem in 2 K-chunks of 128, (hi,lo)-interleaved word pairs,
// row padded +8 words -> conflict-free LDS.64 B-fragment loads.
#define SROW 136   // 128 data words (64 kw pairs) + 8 pad
__global__ __launch_bounds__(256) void gemm_tensor_kernel() {
    __shared__ unsigned sw[64 * SROW];   // 34,816 B

    int bm = blockIdx.y * 128;
    int bn = blockIdx.x * 64;
    int tid  = threadIdx.x;
    int wid  = tid >> 5;
    int lane = tid & 31;
    int grp  = lane >> 2;     // 0..7
    int ctg  = lane & 3;      // 0..3

    int row0 = bm + wid * 16 + grp;
    int row1 = row0 + 8;
    bool v0 = row0 < N_NODES, v1 = row1 < N_NODES;

    float acc[8][4];
    #pragma unroll
    for (int nb = 0; nb < 8; nb++)
        #pragma unroll
        for (int j = 0; j < 4; j++) acc[nb][j] = 0.f;

    #pragma unroll 1
    for (int c = 0; c < 2; c++) {
        __syncthreads();   // previous chunk consumed
        // fill smem: thread t -> n row t/4, 16 kw starting at (t%4)*16
        {
            int nl = tid >> 2;
            int q  = (tid & 3) * 16;
            int gn = bn + nl;
            #pragma unroll
            for (int j = 0; j < 16; j++) {
                int kw = q + j;                       // 0..63 within chunk
                unsigned h = g_wth[gn * DW + c * 64 + kw];
                unsigned l = g_wtl[gn * DW + c * 64 + kw];
                *reinterpret_cast<uint2*>(&sw[nl * SROW + kw * 2]) =
                    make_uint2(h, l);
            }
        }
        __syncthreads();

        #pragma unroll
        for (int ks = 0; ks < 8; ks++) {
            int kwg = c * 64 + ks * 8 + ctg;          // global word idx for a0
            unsigned ah0 = 0, ah1 = 0, ah2 = 0, ah3 = 0;
            unsigned al0 = 0, al1 = 0, al2 = 0, al3 = 0;
            if (v0) {
                ah0 = g_xh[row0 * DW + kwg];  ah2 = g_xh[row0 * DW + kwg + 4];
                al0 = g_xl[row0 * DW + kwg];  al2 = g_xl[row0 * DW + kwg + 4];
            }
            if (v1) {
                ah1 = g_xh[row1 * DW + kwg];  ah3 = g_xh[row1 * DW + kwg + 4];
                al1 = g_xl[row1 * DW + kwg];  al3 = g_xl[row1 * DW + kwg + 4];
            }
            #pragma unroll
            for (int nb = 0; nb < 8; nb++) {
                int base = (nb * 8 + grp) * SROW + (ks * 8 + ctg) * 2;
                uint2 b0 = *reinterpret_cast<const uint2*>(&sw[base]);      // (bh0,bl0)
                uint2 b1 = *reinterpret_cast<const uint2*>(&sw[base + 8]);  // (bh1,bl1)
                float* d = acc[nb];
                asm volatile(
                    "mma.sync.aligned.m16n8k16.row.col.f32.bf16.bf16.f32 "
                    "{%0,%1,%2,%3}, {%4,%5,%6,%7}, {%8,%9}, {%0,%1,%2,%3};"
                    : "+f"(d[0]), "+f"(d[1]), "+f"(d[2]), "+f"(d[3])
                    : "r"(ah0), "r"(ah1), "r"(ah2), "r"(ah3), "r"(b0.x), "r"(b1.x));
                asm volatile(
                    "mma.sync.aligned.m16n8k16.row.col.f32.bf16.bf16.f32 "
                    "{%0,%1,%2,%3}, {%4,%5,%6,%7}, {%8,%9}, {%0,%1,%2,%3};"
                    : "+f"(d[0]), "+f"(d[1]), "+f"(d[2]), "+f"(d[3])
                    : "r"(al0), "r"(al1), "r"(al2), "r"(al3), "r"(b0.x), "r"(b1.x));
                asm volatile(
                    "mma.sync.aligned.m16n8k16.row.col.f32.bf16.bf16.f32 "
                    "{%0,%1,%2,%3}, {%4,%5,%6,%7}, {%8,%9}, {%0,%1,%2,%3};"
                    : "+f"(d[0]), "+f"(d[1]), "+f"(d[2]), "+f"(d[3])
                    : "r"(ah0), "r"(ah1), "r"(ah2), "r"(ah3), "r"(b0.y), "r"(b1.y));
            }
        }
    }

    // epilogue: scale by dinv, convert fp16, store half2 per (row, 2 cols)
    float dv0 = v0 ? g_dinv[row0] : 0.f;
    float dv1 = v1 ? g_dinv[row1] : 0.f;
    #pragma unroll
    for (int nb = 0; nb < 8; nb++) {
        int n = bn + nb * 8 + 2 * ctg;
        if (v0) {
            __half2 h = __floats2half2_rn(acc[nb][0] * dv0, acc[nb][1] * dv0);
            *reinterpret_cast<__half2*>(&g_zh[row0 * D + n]) = h;
        }
        if (v1) {
            __half2 h = __floats2half2_rn(acc[nb][2] * dv1, acc[nb][3] * dv1);
            *reinterpret_cast<__half2*>(&g_zh[row1 * D + n]) = h;
        }
    }
}

// ---------------------------------------------------------------------------
// One block (128 threads) per node i; thread t owns columns 2t, 2t+1.
__global__ __launch_bounds__(128) void agg_kernel(float* __restrict__ out) {
    __shared__ unsigned words[USED_WORDS];
    __shared__ int list[CAP];
    __shared__ int s_count;
    int i = blockIdx.x;
    int t = threadIdx.x;
    if (t == 0) s_count = 0;
    const unsigned* row = &g_bits[i * ROW_WORDS];
    for (int w = t; w < USED_WORDS; w += 128) words[w] = row[w];
    __syncthreads();

    for (int w = t; w < USED_WORDS; w += 128) {
        unsigned m = words[w];
        int n = __popc(m);
        if (n) {
            int base = atomicAdd(&s_count, n);
            while (m) {
                int b = __ffs(m) - 1;
                m &= m - 1;
                if (base < CAP) list[base] = (w << 5) + b;
                base++;
            }
        }
    }
    __syncthreads();

    const __half2* Z = reinterpret_cast<const __half2*>(g_zh);
    float2 self = __half22float2(Z[i * (D / 2) + t]);
    float accx = self.x, accy = self.y;
    int c = s_count;

    if (c <= CAP) {
        int k = 0;
        for (; k + 8 <= c; k += 8) {
            float2 a0 = __half22float2(Z[list[k+0] * (D/2) + t]);
            float2 a1 = __half22float2(Z[list[k+1] * (D/2) + t]);
            float2 a2 = __half22float2(Z[list[k+2] * (D/2) + t]);
            float2 a3 = __half22float2(Z[list[k+3] * (D/2) + t]);
            float2 a4 = __half22float2(Z[list[k+4] * (D/2) + t]);
            float2 a5 = __half22float2(Z[list[k+5] * (D/2) + t]);
            float2 a6 = __half22float2(Z[list[k+6] * (D/2) + t]);
            float2 a7 = __half22float2(Z[list[k+7] * (D/2) + t]);
            accx += ((a0.x + a1.x) + (a2.x + a3.x)) + ((a4.x + a5.x) + (a6.x + a7.x));
            accy += ((a0.y + a1.y) + (a2.y + a3.y)) + ((a4.y + a5.y) + (a6.y + a7.y));
        }
        for (; k < c; k++) {
            float2 a = __half22float2(Z[list[k] * (D/2) + t]);
            accx += a.x; accy += a.y;
        }
    } else {
        #pragma unroll 1
        for (int wi = 0; wi < USED_WORDS; wi++) {
            unsigned w = words[wi];
            while (w) {
                int b = __ffs(w) - 1;
                w &= w - 1;
                float2 a = __half22float2(Z[((wi << 5) + b) * (D/2) + t]);
                accx += a.x; accy += a.y;
            }
        }
    }
    float dv = g_dinv[i];
    *reinterpret_cast<float2*>(&out[i * D + 2 * t]) =
        make_float2(accx * dv, accy * dv);
}

// ---------------------------------------------------------------------------
extern "C" void kernel_launch(void* const* d_in, const int* in_sizes, int n_in,
                              void* d_out, int out_size) {
    const float* x  = nullptr;
    const int*   ei = nullptr;
    const float* w  = nullptr;
    for (int i = 0; i < n_in; i++) {
        if      (in_sizes[i] == N_NODES * D)   x  = (const float*)d_in[i];
        else if (in_sizes[i] == 2 * E_EDGES)   ei = (const int*)d_in[i];
        else if (in_sizes[i] == D * D)         w  = (const float*)d_in[i];
    }
    float* out = (float*)d_out;
    (void)out_size;

    zero_bits_kernel<<<1024, 256>>>();
    split_x_kernel<<<(N_NODES * DW + 255) / 256, 256>>>(x);
    split_w_kernel<<<(D * DW + 255) / 256, 256>>>(w);
    edge_kernel<<<(E_EDGES + 255) / 256, 256>>>(ei);
    degree_kernel<<<(N_NODES * 32 + 255) / 256, 256>>>();
    gemm_tensor_kernel<<<dim3(D / 64, (N_NODES + 127) / 128), 256>>>();
    agg_kernel<<<N_NODES, 128>>>(out);
}